// round 3
// baseline (speedup 1.0000x reference)
#include <cuda_runtime.h>

typedef unsigned long long ull;

#define TT 16
#define DD 8
#define HH 40
#define HP1 41
#define NT 64
#define NTHREADS 256
#define NBLK 296
#define NPAIR_PAD 1024
#define NPAIRS 948
#define PPT 4
#define WSTRIDE 52

// Output offsets (reference tuple order, row-major each)
#define O_BG1 0
#define O_BG2 16
#define O_MU  32
#define O_KAP 160
#define O_NU  176
#define O_PSI 192
#define O_WM  1216
#define O_WS  1872
#define O_ZA  28768
#define O_ZB  28784
#define O_EA  28800
#define O_EB  28816

// Scratch: per-block partials (float pairs packed as ull) + fp64 totals
__device__ ull    g_part[(size_t)NBLK * NPAIR_PAD * 8];
__device__ double g_tot[NPAIR_PAD * TT];

// Pair p -> (ws_i, ws_j) shared-row indices.
// ws layout per row: [x0..x7, 1, h0..h39, y, 0, 0]  (indices 0..51)
// M1 pairs: 45 over {0..8}; M2 pairs: 903 over {8..49}; pad -> (50,50) which is 0.
__device__ __forceinline__ void pair_of(int p, int &wi, int &wj) {
    if (p < 45) {
        int i = 0, rem = p;
        while (rem >= 9 - i) { rem -= 9 - i; ++i; }
        wi = i; wj = i + rem;
    } else if (p < NPAIRS) {
        int q = p - 45, a = 0;
        while (q >= 42 - a) { q -= 42 - a; ++a; }
        wi = 8 + a; wj = 8 + a + q;
    } else {
        wi = 50; wj = 50;
    }
}

// Inverse maps for finalize
__device__ __forceinline__ int pairM1(int i, int j) { return i*9 - (i*(i-1))/2 + (j - i); }          // i<=j in 0..8
__device__ __forceinline__ int pairM2(int a, int b) { return 45 + a*42 - (a*(a-1))/2 + (b - a); }    // a<=b in 0..41 (local)
__device__ __forceinline__ int lmap(int i) { return (i < HH) ? (i + 1) : 0; }                        // X index -> M2 local
__device__ __forceinline__ double totA(int i, int j, int t) {
    int a = lmap(i), b = lmap(j);
    int lo = a < b ? a : b, hi = a < b ? b : a;
    return g_tot[pairM2(lo, hi)*TT + t];
}

__global__ __launch_bounds__(NTHREADS) void k_reduce(
    const float* __restrict__ Phi, const float* __restrict__ Xin,
    const float* __restrict__ Yout, const float* __restrict__ Welm,
    const float* __restrict__ Belm, int n_total)
{
    __shared__ float ws[NT][WSTRIDE];
    __shared__ float phs[NT][TT];
    __shared__ float sW[DD*HH];
    __shared__ float sB[HH];
    const int tid = threadIdx.x;

    for (int i = tid; i < DD*HH; i += NTHREADS) sW[i] = Welm[i];
    if (tid < HH) sB[tid] = Belm[tid];

    int wi[PPT], wj[PPT];
#pragma unroll
    for (int k = 0; k < PPT; ++k) pair_of(tid*PPT + k, wi[k], wj[k]);

    ull acc[PPT][8];
#pragma unroll
    for (int k = 0; k < PPT; ++k)
#pragma unroll
        for (int w = 0; w < 8; ++w) acc[k][w] = 0ull;

    const int stride = NT * gridDim.x;
    const int ntiles = (n_total + stride - 1) / stride;

    for (int tile = 0; tile < ntiles; ++tile) {
        const int n0 = (blockIdx.x + tile * gridDim.x) * NT;
        __syncthreads();
        // load x rows (contiguous)
        for (int idx = tid; idx < NT*DD; idx += NTHREADS) {
            int r = idx >> 3;
            float v = (n0 + r < n_total) ? Xin[(size_t)n0*DD + idx] : 0.f;
            ws[r][idx & 7] = v;
        }
        // load phi rows (contiguous)
        for (int idx = tid; idx < NT*TT; idx += NTHREADS) {
            int r = idx >> 4;
            float v = (n0 + r < n_total) ? Phi[(size_t)n0*TT + idx] : 0.f;
            phs[r][idx & 15] = v;
        }
        // const, y, pad
        for (int r = tid; r < NT; r += NTHREADS) {
            ws[r][8]  = 1.0f;
            ws[r][49] = (n0 + r < n_total) ? Yout[n0 + r] : 0.f;
            ws[r][50] = 0.f; ws[r][51] = 0.f;
        }
        __syncthreads();
        // ELM hidden map: h = sigmoid(x.W + b)   (writes cols 9..48; reads 0..7 -> disjoint)
        for (int q = tid; q < NT*HH; q += NTHREADS) {
            int r = q / HH, h = q - r*HH;
            float z = sB[h];
#pragma unroll
            for (int d = 0; d < DD; ++d) z = fmaf(ws[r][d], sW[d*HH + h], z);
            ws[r][9 + h] = 1.0f / (1.0f + __expf(-z));
        }
        __syncthreads();

        // main accumulation: acc[pair][t2] += phi2[t2] * (v_i*v_j)
#pragma unroll 1
        for (int r = 0; r < NT; ++r) {
            const ull* ph = reinterpret_cast<const ull*>(&phs[r][0]);
            ull pv[8];
#pragma unroll
            for (int w = 0; w < 8; ++w) pv[w] = ph[w];
            const float* row = &ws[r][0];
#pragma unroll
            for (int k = 0; k < PPT; ++k) {
                float prod = row[wi[k]] * row[wj[k]];
                unsigned int pu = __float_as_uint(prod);
                ull pp;
                asm("mov.b64 %0, {%1, %2};" : "=l"(pp) : "r"(pu), "r"(pu));
#pragma unroll
                for (int w = 0; w < 8; ++w)
                    asm("fma.rn.f32x2 %0, %1, %2, %0;" : "+l"(acc[k][w]) : "l"(pv[w]), "l"(pp));
            }
        }
    }

    ull* outp = &g_part[((size_t)blockIdx.x * NPAIR_PAD + (size_t)tid*PPT) * 8];
#pragma unroll
    for (int k = 0; k < PPT; ++k)
#pragma unroll
        for (int w = 0; w < 8; ++w) outp[k*8 + w] = acc[k][w];
}

__global__ void k_sum(int nblk) {
    int e = blockIdx.x * blockDim.x + threadIdx.x;
    if (e >= NPAIR_PAD * TT) return;
    const float* pf = reinterpret_cast<const float*>(g_part);
    double s = 0.0;
    for (int b = 0; b < nblk; ++b) s += (double)pf[(size_t)b * (NPAIR_PAD*TT) + e];
    g_tot[e] = s;
}

__global__ __launch_bounds__(256) void k_final(
    const float* __restrict__ epsA, const float* __restrict__ epsB,
    const float* __restrict__ zetA, const float* __restrict__ zetB,
    float* __restrict__ out)
{
    const int t = blockIdx.x;
    const int tid = threadIdx.x;
    __shared__ double As[HP1][HP1+1];   // eps*A + zet*I  (then eliminated)
    __shared__ double A0[HP1][HP1+1];   // raw A (for epilogue quadratic forms)
    __shared__ double Xs[HP1][HP1+1];   // inverse under construction
    __shared__ double colk[HP1];
    __shared__ double bv[HP1], wm[HP1];

    const double eps = (double)epsA[t] / (double)epsB[t];
    const double zet = (double)zetA[t] / (double)zetB[t];

    // Block 0: all the cheap non-t-parallel outputs (no syncs in here)
    if (blockIdx.x == 0) {
        if (tid < TT) {
            int u = tid;
            double sp = g_tot[44*TT + u];                  // sumPhi[u]  (pairM1(8,8)=44)
            out[O_BG1 + u] = (float)(1.0 + sp);
            out[O_KAP + u] = (float)(1000.0 + sp);
            out[O_NU  + u] = (float)(sp + 100.0);
            out[O_ZA  + u] = zetA[u] + 20.5f;              // + (H+1)/2
            out[O_EA  + u] = (float)(epsA[u] + 0.5 * sp);
            double s2 = 0.0;
            for (int v = u + 1; v < TT; ++v) s2 += g_tot[44*TT + v];
            out[O_BG2 + u] = (float)(1.0 + s2);
        }
        for (int idx = tid; idx < DD*TT; idx += 256) {
            int i = idx >> 4, u = idx & 15;
            double sp = g_tot[44*TT + u];
            out[O_MU + idx] = (float)(g_tot[pairM1(i,8)*TT + u] / (1000.0 + sp));
        }
        for (int idx = tid; idx < DD*DD*TT; idx += 256) {
            int i = idx >> 7, j = (idx >> 4) & 7, u = idx & 15;
            double sp  = g_tot[44*TT + u];
            double kap = 1000.0 + sp;
            double mui = g_tot[pairM1(i,8)*TT + u] / kap;
            double muj = g_tot[pairM1(j,8)*TT + u] / kap;
            int lo = i < j ? i : j, hi = i < j ? j : i;
            double Sij = g_tot[pairM1(lo,hi)*TT + u];
            out[O_PSI + idx] = (float)(((i==j) ? 500.0 : 0.0) + Sij - kap*mui*muj);
        }
    }

    // Build A, M = eps*A + zet*I, X = I   (all fp64)
    for (int idx = tid; idx < HP1*HP1; idx += 256) {
        int i = idx / HP1, j = idx - i*HP1;
        double a = totA(i, j, t);
        A0[i][j] = a;
        As[i][j] = eps*a + ((i==j) ? zet : 0.0);
        Xs[i][j] = (i==j) ? 1.0 : 0.0;
    }
    __syncthreads();

    // Pivot-free Gauss-Jordan in fp64 (M is SPD -> stable without pivoting)
    for (int k = 0; k < HP1; ++k) {
        if (tid < HP1) colk[tid] = As[tid][k];
        __syncthreads();
        double ip = 1.0 / colk[k];
        for (int c = tid; c < HP1; c += 256) { As[k][c] *= ip; Xs[k][c] *= ip; }
        __syncthreads();
        for (int idx = tid; idx < HP1*HP1; idx += 256) {
            int r = idx / HP1, c = idx - r*HP1;
            if (r != k) {
                double f = colk[r];
                As[r][c] = fma(-f, As[k][c], As[r][c]);
                Xs[r][c] = fma(-f, Xs[k][c], Xs[r][c]);
            }
        }
        __syncthreads();
    }

    // b vector, WMv  (fp64)
    if (tid < HP1) bv[tid] = g_tot[pairM2(lmap(tid), HP1)*TT + t];
    __syncthreads();
    if (tid < HP1) {
        double s = 0.0;
        for (int j = 0; j < HP1; ++j) s = fma(Xs[tid][j], bv[j], s);
        wm[tid] = zet * s;
    }
    __syncthreads();

    // WS, WM (cast to fp32 at store)
    for (int idx = tid; idx < HP1*HP1; idx += 256) {
        int i = idx / HP1, j = idx - i*HP1;
        out[O_WS + t*HP1*HP1 + idx] = (float)Xs[i][j];
    }
    if (tid < HP1) out[O_WM + t*HP1 + tid] = (float)wm[tid];

    // zetaB_new, epsB_new (t1 folded algebraically: no second N pass)
    if (tid == 0) {
        double trWS = 0, wm2 = 0, wb = 0, qf = 0, t2 = 0;
        for (int i = 0; i < HP1; ++i) {
            trWS += Xs[i][i];
            wm2  += wm[i] * wm[i];
            wb   += wm[i] * bv[i];
            double qi = 0;
            for (int j = 0; j < HP1; ++j) {
                qi += A0[i][j] * wm[j];
                t2 += A0[i][j] * Xs[j][i];
            }
            qf += wm[i] * qi;
        }
        double cc = g_tot[947*TT + t];                     // pairM2(41,41)=947: sum phi*y^2
        double t1 = cc - 2.0*wb + qf;
        out[O_ZB + t] = (float)(zetB[t] + 0.5*(wm2 + trWS));
        out[O_EB + t] = (float)(epsB[t] + 0.5*(t1 + t2));
    }
}

extern "C" void kernel_launch(void* const* d_in, const int* in_sizes, int n_in,
                              void* d_out, int out_size) {
    const float* Phi  = (const float*)d_in[1];
    const float* Xin  = (const float*)d_in[2];
    const float* Yout = (const float*)d_in[3];
    const float* W    = (const float*)d_in[4];
    const float* B    = (const float*)d_in[5];
    const float* eA   = (const float*)d_in[6];
    const float* eB   = (const float*)d_in[7];
    const float* zA   = (const float*)d_in[8];
    const float* zB   = (const float*)d_in[9];
    int n_total = in_sizes[1] / TT;

    k_reduce<<<NBLK, NTHREADS>>>(Phi, Xin, Yout, W, B, n_total);
    k_sum<<<64, 256>>>(NBLK);
    k_final<<<TT, 256>>>(eA, eB, zA, zB, (float*)d_out);
}

// round 4
// speedup vs baseline: 1.5950x; 1.5950x over previous
#include <cuda_runtime.h>

typedef unsigned long long ull;

#define TT 16
#define DD 8
#define HH 40
#define HP1 41
#define NT 64
#define NTHREADS 256
#define NBLK 296
#define NPAIR_PAD 1024
#define NPAIRS 948
#define PPT 4
#define WSTRIDE 52

// Output offsets (reference tuple order, row-major each)
#define O_BG1 0
#define O_BG2 16
#define O_MU  32
#define O_KAP 160
#define O_NU  176
#define O_PSI 192
#define O_WM  1216
#define O_WS  1872
#define O_ZA  28768
#define O_ZB  28784
#define O_EA  28800
#define O_EB  28816

// Scratch: per-block partials (float pairs packed as ull) + double-float totals
__device__ ull    g_part[(size_t)NBLK * NPAIR_PAD * 8];
__device__ float2 g_tot[NPAIR_PAD * TT];

// ---------------- double-float helpers (all full-rate fp32) ----------------
struct dfv { float h, l; };
__device__ __forceinline__ dfv two_sum(float a, float b) {
    float s = a + b;
    float bb = s - a;
    float e = (a - (s - bb)) + (b - bb);
    dfv r; r.h = s; r.l = e; return r;
}
__device__ __forceinline__ dfv df_norm(float h, float l) {
    float s = h + l;
    float e = l - (s - h);
    dfv r; r.h = s; r.l = e; return r;
}
__device__ __forceinline__ dfv df_add(dfv a, dfv b) {
    dfv s = two_sum(a.h, b.h);
    return df_norm(s.h, s.l + a.l + b.l);
}
__device__ __forceinline__ dfv df_addf(dfv a, float b) {
    dfv s = two_sum(a.h, b);
    return df_norm(s.h, s.l + a.l);
}
__device__ __forceinline__ dfv df_mul(dfv a, dfv b) {
    float p = a.h * b.h;
    float e = fmaf(a.h, b.h, -p);
    e = fmaf(a.h, b.l, e);
    e = fmaf(a.l, b.h, e);
    return df_norm(p, e);
}
__device__ __forceinline__ dfv df_mulf(dfv a, float b) {
    float p = a.h * b;
    float e = fmaf(a.h, b, -p);
    e = fmaf(a.l, b, e);
    return df_norm(p, e);
}
__device__ __forceinline__ dfv dtot(int idx) {
    float2 v = g_tot[idx];
    dfv r; r.h = v.x; r.l = v.y; return r;
}

// Pair p -> (ws_i, ws_j) shared-row indices.
__device__ __forceinline__ void pair_of(int p, int &wi, int &wj) {
    if (p < 45) {
        int i = 0, rem = p;
        while (rem >= 9 - i) { rem -= 9 - i; ++i; }
        wi = i; wj = i + rem;
    } else if (p < NPAIRS) {
        int q = p - 45, a = 0;
        while (q >= 42 - a) { q -= 42 - a; ++a; }
        wi = 8 + a; wj = 8 + a + q;
    } else {
        wi = 50; wj = 50;
    }
}

// Inverse maps for finalize
__device__ __forceinline__ int pairM1(int i, int j) { return i*9 - (i*(i-1))/2 + (j - i); }
__device__ __forceinline__ int pairM2(int a, int b) { return 45 + a*42 - (a*(a-1))/2 + (b - a); }
__device__ __forceinline__ int lmap(int i) { return (i < HH) ? (i + 1) : 0; }

__global__ __launch_bounds__(NTHREADS) void k_reduce(
    const float* __restrict__ Phi, const float* __restrict__ Xin,
    const float* __restrict__ Yout, const float* __restrict__ Welm,
    const float* __restrict__ Belm, int n_total)
{
    __shared__ float ws[NT][WSTRIDE];
    __shared__ float phs[NT][TT];
    __shared__ float sW[DD*HH];
    __shared__ float sB[HH];
    const int tid = threadIdx.x;

    for (int i = tid; i < DD*HH; i += NTHREADS) sW[i] = Welm[i];
    if (tid < HH) sB[tid] = Belm[tid];

    int wi[PPT], wj[PPT];
#pragma unroll
    for (int k = 0; k < PPT; ++k) pair_of(tid*PPT + k, wi[k], wj[k]);

    ull acc[PPT][8];
#pragma unroll
    for (int k = 0; k < PPT; ++k)
#pragma unroll
        for (int w = 0; w < 8; ++w) acc[k][w] = 0ull;

    const int stride = NT * gridDim.x;
    const int ntiles = (n_total + stride - 1) / stride;

    for (int tile = 0; tile < ntiles; ++tile) {
        const int n0 = (blockIdx.x + tile * gridDim.x) * NT;
        __syncthreads();
        for (int idx = tid; idx < NT*DD; idx += NTHREADS) {
            int r = idx >> 3;
            float v = (n0 + r < n_total) ? Xin[(size_t)n0*DD + idx] : 0.f;
            ws[r][idx & 7] = v;
        }
        for (int idx = tid; idx < NT*TT; idx += NTHREADS) {
            int r = idx >> 4;
            float v = (n0 + r < n_total) ? Phi[(size_t)n0*TT + idx] : 0.f;
            phs[r][idx & 15] = v;
        }
        for (int r = tid; r < NT; r += NTHREADS) {
            ws[r][8]  = 1.0f;
            ws[r][49] = (n0 + r < n_total) ? Yout[n0 + r] : 0.f;
            ws[r][50] = 0.f; ws[r][51] = 0.f;
        }
        __syncthreads();
        for (int q = tid; q < NT*HH; q += NTHREADS) {
            int r = q / HH, h = q - r*HH;
            float z = sB[h];
#pragma unroll
            for (int d = 0; d < DD; ++d) z = fmaf(ws[r][d], sW[d*HH + h], z);
            ws[r][9 + h] = 1.0f / (1.0f + __expf(-z));
        }
        __syncthreads();

#pragma unroll 1
        for (int r = 0; r < NT; ++r) {
            const ull* ph = reinterpret_cast<const ull*>(&phs[r][0]);
            ull pv[8];
#pragma unroll
            for (int w = 0; w < 8; ++w) pv[w] = ph[w];
            const float* row = &ws[r][0];
#pragma unroll
            for (int k = 0; k < PPT; ++k) {
                float prod = row[wi[k]] * row[wj[k]];
                unsigned int pu = __float_as_uint(prod);
                ull pp;
                asm("mov.b64 %0, {%1, %2};" : "=l"(pp) : "r"(pu), "r"(pu));
#pragma unroll
                for (int w = 0; w < 8; ++w)
                    asm("fma.rn.f32x2 %0, %1, %2, %0;" : "+l"(acc[k][w]) : "l"(pv[w]), "l"(pp));
            }
        }
    }

    ull* outp = &g_part[((size_t)blockIdx.x * NPAIR_PAD + (size_t)tid*PPT) * 8];
#pragma unroll
    for (int k = 0; k < PPT; ++k)
#pragma unroll
        for (int w = 0; w < 8; ++w) outp[k*8 + w] = acc[k][w];
}

// Compensated fp32 cross-block sum (no fp64: DFMA rt is ~18 cyc/SMSP on sm_103a)
__global__ void k_sum(int nblk) {
    int e = blockIdx.x * blockDim.x + threadIdx.x;
    if (e >= NPAIR_PAD * TT) return;
    const float* pf = reinterpret_cast<const float*>(g_part);
    float sh = 0.f, sl = 0.f;
    for (int b = 0; b < nblk; ++b) {
        float x = pf[(size_t)b * (NPAIR_PAD*TT) + e];
        float s = sh + x;
        float bb = s - sh;
        float err = (sh - (s - bb)) + (x - bb);
        sh = s; sl += err;
    }
    g_tot[e] = make_float2(sh, sl);
}

__global__ __launch_bounds__(256) void k_final(
    const float* __restrict__ epsA, const float* __restrict__ epsB,
    const float* __restrict__ zetA, const float* __restrict__ zetB,
    float* __restrict__ out)
{
    const int t = blockIdx.x;
    const int tid = threadIdx.x;
    __shared__ float Mh[HP1][HP1+1], Ml[HP1][HP1+1];   // M = eps*A + zet*I (double-float)
    __shared__ float Xs[HP1][HP1+1];                   // inverse estimate
    __shared__ float Rs[HP1][HP1+1];                   // residual
    __shared__ float Ts[HP1][HP1+1];                   // GJ workspace / correction
    __shared__ float colk[HP1];
    __shared__ float bvh[HP1], bvl[HP1], wmv[HP1];
    __shared__ float4 red[256];

    const float eps = __fdiv_rn(epsA[t], epsB[t]);
    const float zet = __fdiv_rn(zetA[t], zetB[t]);

    // Block 0: cheap non-t-parallel outputs (double-float, no fp64)
    if (blockIdx.x == 0) {
        if (tid < TT) {
            int u = tid;
            dfv sp = dtot(44*TT + u);                    // sumPhi[u]
            out[O_BG1 + u] = df_addf(sp, 1.0f).h;
            out[O_KAP + u] = df_addf(sp, 1000.0f).h;
            out[O_NU  + u] = df_addf(sp, 100.0f).h;
            out[O_ZA  + u] = zetA[u] + 20.5f;
            out[O_EA  + u] = df_addf(df_mulf(sp, 0.5f), epsA[u]).h;
            dfv s2; s2.h = 0.f; s2.l = 0.f;
            for (int v = u + 1; v < TT; ++v) s2 = df_add(s2, dtot(44*TT + v));
            out[O_BG2 + u] = df_addf(s2, 1.0f).h;
        }
        for (int idx = tid; idx < DD*TT; idx += 256) {
            int i = idx >> 4, u = idx & 15;
            dfv kap = df_addf(dtot(44*TT + u), 1000.0f);
            out[O_MU + idx] = __fdiv_rn(dtot(pairM1(i,8)*TT + u).h, kap.h);
        }
        // psi_ij = 500*delta + S_ij - t12_i*t12_j/kap  (double-float, refined division)
        for (int idx = tid; idx < DD*DD*TT; idx += 256) {
            int i = idx >> 7, j = (idx >> 4) & 7, u = idx & 15;
            dfv kap = df_addf(dtot(44*TT + u), 1000.0f);
            dfv t12i = dtot(pairM1(i,8)*TT + u);
            dfv t12j = dtot(pairM1(j,8)*TT + u);
            int lo = i < j ? i : j, hi = i < j ? j : i;
            dfv Sij = dtot(pairM1(lo,hi)*TT + u);
            dfv num = df_mul(t12i, t12j);
            float q0 = __fdiv_rn(num.h, kap.h);
            dfv rem = df_add(num, df_mulf(kap, -q0));
            float q1 = __fdiv_rn(rem.h + rem.l, kap.h);
            dfv s1 = two_sum(Sij.h, -q0);
            float psi = s1.h + (s1.l + Sij.l - q1) + ((i==j) ? 500.0f : 0.0f);
            out[O_PSI + idx] = psi;
        }
    }

    // Build M (double-float): M = eps*A + zet*I.  A_ij = tot(pairM2(lmap(i),lmap(j)))
    for (int idx = tid; idx < HP1*HP1; idx += 256) {
        int i = idx / HP1, j = idx - i*HP1;
        int a = lmap(i), b = lmap(j);
        int lo = a < b ? a : b, hi = a < b ? b : a;
        dfv A = dtot(pairM2(lo, hi)*TT + t);
        dfv M = df_mulf(A, eps);
        if (i == j) M = df_addf(M, zet);
        Mh[i][j] = M.h; Ml[i][j] = M.l;
        Ts[i][j] = M.h;                   // GJ working copy (fp32 seed)
        Xs[i][j] = (i==j) ? 1.f : 0.f;
    }
    __syncthreads();

    // fp32 pivot-free Gauss-Jordan seed (M is SPD)
    for (int k = 0; k < HP1; ++k) {
        if (tid < HP1) colk[tid] = Ts[tid][k];
        __syncthreads();
        float ip = __frcp_rn(colk[k]);
        for (int c = tid; c < HP1; c += 256) { Ts[k][c] *= ip; Xs[k][c] *= ip; }
        __syncthreads();
        for (int idx = tid; idx < HP1*HP1; idx += 256) {
            int r = idx / HP1, c = idx - r*HP1;
            if (r != k) {
                float f = colk[r];
                Ts[r][c] = fmaf(-f, Ts[k][c], Ts[r][c]);
                Xs[r][c] = fmaf(-f, Xs[k][c], Xs[r][c]);
            }
        }
        __syncthreads();
    }

    // 3 Newton steps with double-float residual: R = I - M*X; X += X*R
    for (int it = 0; it < 3; ++it) {
        for (int idx = tid; idx < HP1*HP1; idx += 256) {
            int i = idx / HP1, j = idx - i*HP1;
            float sh = 0.f, sl = 0.f;
#pragma unroll 1
            for (int k = 0; k < HP1; ++k) {
                float mh = Mh[i][k], x = Xs[k][j];
                float p = mh * x;
                float e = fmaf(mh, x, -p);
                e = fmaf(Ml[i][k], x, e);
                float s = sh + p;
                float bb = s - sh;
                float err = (sh - (s - bb)) + (p - bb);
                sh = s; sl += err + e;
            }
            float d = (i==j) ? 1.f : 0.f;
            dfv r = two_sum(d, -sh);
            Rs[i][j] = r.h + (r.l - sl);
        }
        __syncthreads();
        for (int idx = tid; idx < HP1*HP1; idx += 256) {
            int i = idx / HP1, j = idx - i*HP1;
            float s = 0.f;
#pragma unroll 1
            for (int k = 0; k < HP1; ++k) s = fmaf(Xs[i][k], Rs[k][j], s);
            Ts[i][j] = s;
        }
        __syncthreads();
        for (int idx = tid; idx < HP1*HP1; idx += 256) {
            int i = idx / HP1, j = idx - i*HP1;
            Xs[i][j] += Ts[i][j];
        }
        __syncthreads();
    }

    // b vector (df) and WMv = zet * X b  (df dot)
    if (tid < HP1) {
        dfv b = dtot(pairM2(lmap(tid), HP1)*TT + t);
        bvh[tid] = b.h; bvl[tid] = b.l;
    }
    __syncthreads();
    if (tid < HP1) {
        float sh = 0.f, sl = 0.f;
        for (int j = 0; j < HP1; ++j) {
            float x = Xs[tid][j];
            float p = x * bvh[j];
            float e = fmaf(x, bvh[j], -p);
            e = fmaf(x, bvl[j], e);
            float s = sh + p;
            float bb = s - sh;
            float err = (sh - (s - bb)) + (p - bb);
            sh = s; sl += err + e;
        }
        float wm = zet * (sh + sl);
        wmv[tid] = wm;
        out[O_WM + t*HP1 + tid] = wm;
    }
    __syncthreads();

    // WS output
    for (int idx = tid; idx < HP1*HP1; idx += 256) {
        int i = idx / HP1, j = idx - i*HP1;
        out[O_WS + t*HP1*HP1 + idx] = Xs[i][j];
    }

    // Epilogue: t2e = sum_ij M_ij X_ji ; wMw = sum_ij wm_i M_ij wm_j  (df partials)
    {
        float ah = 0.f, al = 0.f, bh2 = 0.f, bl2 = 0.f;
        for (int idx = tid; idx < HP1*HP1; idx += 256) {
            int i = idx / HP1, j = idx - i*HP1;
            float mh = Mh[i][j], ml = Ml[i][j];
            float x = Xs[j][i];
            float p = mh * x;
            float e = fmaf(mh, x, -p);
            e = fmaf(ml, x, e);
            { float s = ah + p; float bb = s - ah;
              float err = (ah - (s - bb)) + (p - bb);
              ah = s; al += err + e; }
            float w2 = wmv[i] * wmv[j];
            float p2 = mh * w2;
            float e2 = fmaf(mh, w2, -p2);
            e2 = fmaf(ml, w2, e2);
            { float s = bh2 + p2; float bb = s - bh2;
              float err = (bh2 - (s - bb)) + (p2 - bb);
              bh2 = s; bl2 += err + e2; }
        }
        red[tid] = make_float4(ah, al, bh2, bl2);
    }
    __syncthreads();

    if (tid == 0) {
        dfv t2e; t2e.h = 0.f; t2e.l = 0.f;
        dfv wMw; wMw.h = 0.f; wMw.l = 0.f;
        for (int k = 0; k < 256; ++k) {
            float4 v = red[k];
            dfv a; a.h = v.x; a.l = v.y;
            dfv b; b.h = v.z; b.l = v.w;
            t2e = df_add(t2e, a);
            wMw = df_add(wMw, b);
        }
        dfv trX; trX.h = 0.f; trX.l = 0.f;
        dfv wm2; wm2.h = 0.f; wm2.l = 0.f;
        dfv wb;  wb.h = 0.f;  wb.l = 0.f;
        for (int i = 0; i < HP1; ++i) {
            trX = df_addf(trX, Xs[i][i]);
            float w = wmv[i];
            trX.h = trX.h;  // no-op
            dfv ww; ww.h = w * w; ww.l = fmaf(w, w, -ww.h);
            wm2 = df_add(wm2, ww);
            dfv bvi; bvi.h = bvh[i]; bvi.l = bvl[i];
            wb = df_add(wb, df_mulf(bvi, w));
        }
        float inv_eps = __frcp_rn(eps);
        // t2 = (t2e - zet*trX)/eps ; qf = (wMw - zet*wm2)/eps
        dfv t2 = df_mulf(df_add(t2e, df_mulf(trX, -zet)), inv_eps);
        dfv qf = df_mulf(df_add(wMw, df_mulf(wm2, -zet)), inv_eps);
        dfv cc = dtot(947*TT + t);                        // sum phi*y^2
        dfv t1 = df_add(df_add(cc, df_mulf(wb, -2.0f)), qf);
        dfv zb = df_addf(df_mulf(df_add(wm2, trX), 0.5f), zetB[t]);
        dfv eb = df_addf(df_mulf(df_add(t1, t2), 0.5f), epsB[t]);
        out[O_ZB + t] = zb.h;
        out[O_EB + t] = eb.h;
    }
}

extern "C" void kernel_launch(void* const* d_in, const int* in_sizes, int n_in,
                              void* d_out, int out_size) {
    const float* Phi  = (const float*)d_in[1];
    const float* Xin  = (const float*)d_in[2];
    const float* Yout = (const float*)d_in[3];
    const float* W    = (const float*)d_in[4];
    const float* B    = (const float*)d_in[5];
    const float* eA   = (const float*)d_in[6];
    const float* eB   = (const float*)d_in[7];
    const float* zA   = (const float*)d_in[8];
    const float* zB   = (const float*)d_in[9];
    int n_total = in_sizes[1] / TT;

    k_reduce<<<NBLK, NTHREADS>>>(Phi, Xin, Yout, W, B, n_total);
    k_sum<<<64, 256>>>(NBLK);
    k_final<<<TT, 256>>>(eA, eB, zA, zB, (float*)d_out);
}

// round 5
// speedup vs baseline: 2.0116x; 1.2611x over previous
#include <cuda_runtime.h>

typedef unsigned long long ull;

#define TT 16
#define DD 8
#define HH 40
#define HP1 41
#define NT 64
#define NTHREADS 256
#define NBLK 296
#define NPAIR_PAD 1024
#define NPAIRS 948
#define PPT 4
#define WSTRIDE 52

// Output offsets (reference tuple order, row-major each)
#define O_BG1 0
#define O_BG2 16
#define O_MU  32
#define O_KAP 160
#define O_NU  176
#define O_PSI 192
#define O_WM  1216
#define O_WS  1872
#define O_ZA  28768
#define O_ZB  28784
#define O_EA  28800
#define O_EB  28816

__device__ ull    g_part[(size_t)NBLK * NPAIR_PAD * 8];
__device__ float2 g_tot[NPAIR_PAD * TT];

// ---------------- double-float helpers (all full-rate fp32) ----------------
struct dfv { float h, l; };
__device__ __forceinline__ dfv two_sum(float a, float b) {
    float s = a + b;
    float bb = s - a;
    float e = (a - (s - bb)) + (b - bb);
    dfv r; r.h = s; r.l = e; return r;
}
__device__ __forceinline__ dfv df_norm(float h, float l) {
    float s = h + l;
    float e = l - (s - h);
    dfv r; r.h = s; r.l = e; return r;
}
__device__ __forceinline__ dfv df_add(dfv a, dfv b) {
    dfv s = two_sum(a.h, b.h);
    return df_norm(s.h, s.l + a.l + b.l);
}
__device__ __forceinline__ dfv df_addf(dfv a, float b) {
    dfv s = two_sum(a.h, b);
    return df_norm(s.h, s.l + a.l);
}
__device__ __forceinline__ dfv df_mul(dfv a, dfv b) {
    float p = a.h * b.h;
    float e = fmaf(a.h, b.h, -p);
    e = fmaf(a.h, b.l, e);
    e = fmaf(a.l, b.h, e);
    return df_norm(p, e);
}
__device__ __forceinline__ dfv df_mulf(dfv a, float b) {
    float p = a.h * b;
    float e = fmaf(a.h, b, -p);
    e = fmaf(a.l, b, e);
    return df_norm(p, e);
}
__device__ __forceinline__ dfv dtot(int idx) {
    float2 v = g_tot[idx];
    dfv r; r.h = v.x; r.l = v.y; return r;
}

__device__ __forceinline__ void pair_of(int p, int &wi, int &wj) {
    if (p < 45) {
        int i = 0, rem = p;
        while (rem >= 9 - i) { rem -= 9 - i; ++i; }
        wi = i; wj = i + rem;
    } else if (p < NPAIRS) {
        int q = p - 45, a = 0;
        while (q >= 42 - a) { q -= 42 - a; ++a; }
        wi = 8 + a; wj = 8 + a + q;
    } else {
        wi = 50; wj = 50;
    }
}

__device__ __forceinline__ int pairM1(int i, int j) { return i*9 - (i*(i-1))/2 + (j - i); }
__device__ __forceinline__ int pairM2(int a, int b) { return 45 + a*42 - (a*(a-1))/2 + (b - a); }
__device__ __forceinline__ int lmap(int i) { return (i < HH) ? (i + 1) : 0; }

__global__ __launch_bounds__(NTHREADS, 2) void k_reduce(
    const float* __restrict__ Phi, const float* __restrict__ Xin,
    const float* __restrict__ Yout, const float* __restrict__ Welm,
    const float* __restrict__ Belm, int n_total)
{
    __shared__ __align__(16) float ws[NT][WSTRIDE];
    __shared__ __align__(16) float phs[NT][TT];
    __shared__ float sW[DD*HH];
    __shared__ float sB[HH];
    const int tid = threadIdx.x;

    for (int i = tid; i < DD*HH; i += NTHREADS) sW[i] = Welm[i];
    if (tid < HH) sB[tid] = Belm[tid];

    int wi[PPT], wj[PPT];
#pragma unroll
    for (int k = 0; k < PPT; ++k) pair_of(tid*PPT + k, wi[k], wj[k]);

    ull acc[PPT][8];
#pragma unroll
    for (int k = 0; k < PPT; ++k)
#pragma unroll
        for (int w = 0; w < 8; ++w) acc[k][w] = 0ull;

    const int stride = NT * gridDim.x;
    const int ntiles = (n_total + stride - 1) / stride;

    for (int tile = 0; tile < ntiles; ++tile) {
        const int n0 = (blockIdx.x + tile * gridDim.x) * NT;
        __syncthreads();
        for (int idx = tid; idx < NT*DD; idx += NTHREADS) {
            int r = idx >> 3;
            float v = (n0 + r < n_total) ? Xin[(size_t)n0*DD + idx] : 0.f;
            ws[r][idx & 7] = v;
        }
        for (int idx = tid; idx < NT*TT; idx += NTHREADS) {
            int r = idx >> 4;
            float v = (n0 + r < n_total) ? Phi[(size_t)n0*TT + idx] : 0.f;
            phs[r][idx & 15] = v;
        }
        for (int r = tid; r < NT; r += NTHREADS) {
            ws[r][8]  = 1.0f;
            ws[r][49] = (n0 + r < n_total) ? Yout[n0 + r] : 0.f;
            ws[r][50] = 0.f; ws[r][51] = 0.f;
        }
        __syncthreads();
        for (int q = tid; q < NT*HH; q += NTHREADS) {
            int r = q / HH, h = q - r*HH;
            float z = sB[h];
#pragma unroll
            for (int d = 0; d < DD; ++d) z = fmaf(ws[r][d], sW[d*HH + h], z);
            ws[r][9 + h] = 1.0f / (1.0f + __expf(-z));
        }
        __syncthreads();

#pragma unroll 2
        for (int r = 0; r < NT; ++r) {
            // phi row as 4x LDS.128 (rows are 64B, 16B-aligned)
            const ulonglong2* ph2 = reinterpret_cast<const ulonglong2*>(&phs[r][0]);
            ulonglong2 qa = ph2[0], qb = ph2[1], qc = ph2[2], qd = ph2[3];
            ull pv[8];
            pv[0]=qa.x; pv[1]=qa.y; pv[2]=qb.x; pv[3]=qb.y;
            pv[4]=qc.x; pv[5]=qc.y; pv[6]=qd.x; pv[7]=qd.y;
            const float* row = &ws[r][0];
#pragma unroll
            for (int k = 0; k < PPT; ++k) {
                float prod = row[wi[k]] * row[wj[k]];
                unsigned int pu = __float_as_uint(prod);
                ull pp;
                asm("mov.b64 %0, {%1, %2};" : "=l"(pp) : "r"(pu), "r"(pu));
#pragma unroll
                for (int w = 0; w < 8; ++w)
                    asm("fma.rn.f32x2 %0, %1, %2, %0;" : "+l"(acc[k][w]) : "l"(pv[w]), "l"(pp));
            }
        }
    }

    ull* outp = &g_part[((size_t)blockIdx.x * NPAIR_PAD + (size_t)tid*PPT) * 8];
#pragma unroll
    for (int k = 0; k < PPT; ++k)
#pragma unroll
        for (int w = 0; w < 8; ++w) outp[k*8 + w] = acc[k][w];
}

// Parallel compensated cross-block sum: 4 threads per output + fixed-order shfl combine
__global__ __launch_bounds__(256) void k_sum(int nblk) {
    int gid = blockIdx.x * blockDim.x + threadIdx.x;   // 0..65535
    int e = gid >> 2, q = gid & 3;
    const float* pf = reinterpret_cast<const float*>(g_part);
    float sh = 0.f, sl = 0.f;
    for (int b = q; b < nblk; b += 4) {
        float x = pf[(size_t)b * (NPAIR_PAD*TT) + e];
        float s = sh + x;
        float bb = s - sh;
        float err = (sh - (s - bb)) + (x - bb);
        sh = s; sl += err;
    }
    // combine q partials in fixed order: ((q0+q1)+(q2+q3))
    float oh = __shfl_down_sync(0xffffffffu, sh, 1);
    float ol = __shfl_down_sync(0xffffffffu, sl, 1);
    dfv a; a.h = sh; a.l = sl;
    if ((q & 1) == 0) { dfv bb; bb.h = oh; bb.l = ol; a = df_add(a, bb); }
    oh = __shfl_down_sync(0xffffffffu, a.h, 2);
    ol = __shfl_down_sync(0xffffffffu, a.l, 2);
    if (q == 0) {
        dfv bb; bb.h = oh; bb.l = ol; a = df_add(a, bb);
        g_tot[e] = make_float2(a.h, a.l);
    }
}

__global__ __launch_bounds__(256) void k_final(
    const float* __restrict__ epsA, const float* __restrict__ epsB,
    const float* __restrict__ zetA, const float* __restrict__ zetB,
    float* __restrict__ out)
{
    const int t = blockIdx.x;
    const int tid = threadIdx.x;
    __shared__ float Mh[HP1][HP1+1], Ml[HP1][HP1+1];
    __shared__ float Xs[HP1][HP1+1];
    __shared__ float Rs[HP1][HP1+1];
    __shared__ float Ts[HP1][HP1+1];
    __shared__ float colk[HP1], rowkT[HP1], rowkX[HP1];
    __shared__ float bvh[HP1], bvl[HP1], wmv[HP1];
    __shared__ float4 red[8];

    const float eps = __fdiv_rn(epsA[t], epsB[t]);
    const float zet = __fdiv_rn(zetA[t], zetB[t]);

    // Per-t slice of the cheap outputs (balanced across all 16 blocks)
    if (tid == 0) {
        dfv sp = dtot(44*TT + t);                    // sumPhi[t]
        out[O_BG1 + t] = df_addf(sp, 1.0f).h;
        out[O_KAP + t] = df_addf(sp, 1000.0f).h;
        out[O_NU  + t] = df_addf(sp, 100.0f).h;
        out[O_ZA  + t] = zetA[t] + 20.5f;
        out[O_EA  + t] = df_addf(df_mulf(sp, 0.5f), epsA[t]).h;
        dfv s2; s2.h = 0.f; s2.l = 0.f;
        for (int v = t + 1; v < TT; ++v) s2 = df_add(s2, dtot(44*TT + v));
        out[O_BG2 + t] = df_addf(s2, 1.0f).h;
    }
    if (tid >= 32 && tid < 32 + DD) {
        int i = tid - 32;
        dfv kap = df_addf(dtot(44*TT + t), 1000.0f);
        out[O_MU + i*TT + t] = __fdiv_rn(dtot(pairM1(i,8)*TT + t).h, kap.h);
    }
    if (tid >= 64 && tid < 128) {
        int i = (tid - 64) >> 3, j = (tid - 64) & 7;
        dfv kap = df_addf(dtot(44*TT + t), 1000.0f);
        dfv t12i = dtot(pairM1(i,8)*TT + t);
        dfv t12j = dtot(pairM1(j,8)*TT + t);
        int lo = i < j ? i : j, hi = i < j ? j : i;
        dfv Sij = dtot(pairM1(lo,hi)*TT + t);
        dfv num = df_mul(t12i, t12j);
        float q0 = __fdiv_rn(num.h, kap.h);
        dfv rem = df_add(num, df_mulf(kap, -q0));
        float q1 = __fdiv_rn(rem.h + rem.l, kap.h);
        dfv s1 = two_sum(Sij.h, -q0);
        float psi = s1.h + (s1.l + Sij.l - q1) + ((i==j) ? 500.0f : 0.0f);
        out[O_PSI + i*DD*TT + j*TT + t] = psi;
    }

    // Build M (double-float): M = eps*A + zet*I
    for (int idx = tid; idx < HP1*HP1; idx += 256) {
        int i = idx / HP1, j = idx - i*HP1;
        int a = lmap(i), b = lmap(j);
        int lo = a < b ? a : b, hi = a < b ? b : a;
        dfv A = dtot(pairM2(lo, hi)*TT + t);
        dfv M = df_mulf(A, eps);
        if (i == j) M = df_addf(M, zet);
        Mh[i][j] = M.h; Ml[i][j] = M.l;
        Ts[i][j] = M.h;
        Xs[i][j] = (i==j) ? 1.f : 0.f;
    }
    __syncthreads();

    // fp32 pivot-free Gauss-Jordan seed (2 syncs per iteration)
    for (int k = 0; k < HP1; ++k) {
        if (tid < HP1) colk[tid] = Ts[tid][k];
        else if (tid >= 64 && tid < 64 + HP1) rowkT[tid - 64] = Ts[k][tid - 64];
        else if (tid >= 128 && tid < 128 + HP1) rowkX[tid - 128] = Xs[k][tid - 128];
        __syncthreads();
        float ip = __frcp_rn(colk[k]);
        for (int idx = tid; idx < HP1*HP1; idx += 256) {
            int r = idx / HP1, c = idx - r*HP1;
            float rsT = rowkT[c] * ip;
            float rsX = rowkX[c] * ip;
            if (r == k) { Ts[r][c] = rsT; Xs[r][c] = rsX; }
            else {
                float f = colk[r];
                Ts[r][c] = fmaf(-f, rsT, Ts[r][c]);
                Xs[r][c] = fmaf(-f, rsX, Xs[r][c]);
            }
        }
        __syncthreads();
    }

    // 3 Newton steps with double-float residual: R = I - M*X; X += X*R
    for (int it = 0; it < 3; ++it) {
        for (int idx = tid; idx < HP1*HP1; idx += 256) {
            int i = idx / HP1, j = idx - i*HP1;
            float sh = 0.f, sl = 0.f;
            for (int k = 0; k < HP1; ++k) {
                float mh = Mh[i][k], x = Xs[k][j];
                float p = mh * x;
                float e = fmaf(mh, x, -p);
                e = fmaf(Ml[i][k], x, e);
                float s = sh + p;
                float bb = s - sh;
                float err = (sh - (s - bb)) + (p - bb);
                sh = s; sl += err + e;
            }
            float d = (i==j) ? 1.f : 0.f;
            dfv r = two_sum(d, -sh);
            Rs[i][j] = r.h + (r.l - sl);
        }
        __syncthreads();
        for (int idx = tid; idx < HP1*HP1; idx += 256) {
            int i = idx / HP1, j = idx - i*HP1;
            float s = 0.f;
            for (int k = 0; k < HP1; ++k) s = fmaf(Xs[i][k], Rs[k][j], s);
            Ts[i][j] = s;
        }
        __syncthreads();
        for (int idx = tid; idx < HP1*HP1; idx += 256) {
            int i = idx / HP1, j = idx - i*HP1;
            Xs[i][j] += Ts[i][j];
        }
        __syncthreads();
    }

    // b vector (df) and WMv = zet * X b  (df dot)
    if (tid < HP1) {
        dfv b = dtot(pairM2(lmap(tid), HP1)*TT + t);
        bvh[tid] = b.h; bvl[tid] = b.l;
    }
    __syncthreads();
    if (tid < HP1) {
        float sh = 0.f, sl = 0.f;
        for (int j = 0; j < HP1; ++j) {
            float x = Xs[tid][j];
            float p = x * bvh[j];
            float e = fmaf(x, bvh[j], -p);
            e = fmaf(x, bvl[j], e);
            float s = sh + p;
            float bb = s - sh;
            float err = (sh - (s - bb)) + (p - bb);
            sh = s; sl += err + e;
        }
        float wm = zet * (sh + sl);
        wmv[tid] = wm;
        out[O_WM + t*HP1 + tid] = wm;
    }
    __syncthreads();

    for (int idx = tid; idx < HP1*HP1; idx += 256) {
        int i = idx / HP1, j = idx - i*HP1;
        out[O_WS + t*HP1*HP1 + idx] = Xs[i][j];
    }

    // Epilogue partials: t2e = sum_ij M_ij X_ji ; wMw = sum_ij wm_i M_ij wm_j
    float ah = 0.f, al = 0.f, bh2 = 0.f, bl2 = 0.f;
    for (int idx = tid; idx < HP1*HP1; idx += 256) {
        int i = idx / HP1, j = idx - i*HP1;
        float mh = Mh[i][j], ml = Ml[i][j];
        float x = Xs[j][i];
        float p = mh * x;
        float e = fmaf(mh, x, -p);
        e = fmaf(ml, x, e);
        { float s = ah + p; float bb = s - ah;
          float err = (ah - (s - bb)) + (p - bb);
          ah = s; al += err + e; }
        float w2 = wmv[i] * wmv[j];
        float p2 = mh * w2;
        float e2 = fmaf(mh, w2, -p2);
        e2 = fmaf(ml, w2, e2);
        { float s = bh2 + p2; float bb = s - bh2;
          float err = (bh2 - (s - bb)) + (p2 - bb);
          bh2 = s; bl2 += err + e2; }
    }
    // warp tree reduce (deterministic fixed order), then 8-way combine
    {
        dfv a; a.h = ah; a.l = al;
        dfv b; b.h = bh2; b.l = bl2;
#pragma unroll
        for (int off = 16; off > 0; off >>= 1) {
            float xh = __shfl_down_sync(0xffffffffu, a.h, off);
            float xl = __shfl_down_sync(0xffffffffu, a.l, off);
            float yh = __shfl_down_sync(0xffffffffu, b.h, off);
            float yl = __shfl_down_sync(0xffffffffu, b.l, off);
            dfv xa; xa.h = xh; xa.l = xl;
            dfv yb; yb.h = yh; yb.l = yl;
            a = df_add(a, xa);
            b = df_add(b, yb);
        }
        if ((tid & 31) == 0) red[tid >> 5] = make_float4(a.h, a.l, b.h, b.l);
    }
    __syncthreads();

    if (tid == 0) {
        dfv t2e; t2e.h = 0.f; t2e.l = 0.f;
        dfv wMw; wMw.h = 0.f; wMw.l = 0.f;
        for (int k = 0; k < 8; ++k) {
            float4 v = red[k];
            dfv a; a.h = v.x; a.l = v.y;
            dfv b; b.h = v.z; b.l = v.w;
            t2e = df_add(t2e, a);
            wMw = df_add(wMw, b);
        }
        dfv trX; trX.h = 0.f; trX.l = 0.f;
        dfv wm2; wm2.h = 0.f; wm2.l = 0.f;
        dfv wb;  wb.h = 0.f;  wb.l = 0.f;
        for (int i = 0; i < HP1; ++i) {
            trX = df_addf(trX, Xs[i][i]);
            float w = wmv[i];
            dfv ww; ww.h = w * w; ww.l = fmaf(w, w, -ww.h);
            wm2 = df_add(wm2, ww);
            dfv bvi; bvi.h = bvh[i]; bvi.l = bvl[i];
            wb = df_add(wb, df_mulf(bvi, w));
        }
        float inv_eps = __frcp_rn(eps);
        dfv t2 = df_mulf(df_add(t2e, df_mulf(trX, -zet)), inv_eps);
        dfv qf = df_mulf(df_add(wMw, df_mulf(wm2, -zet)), inv_eps);
        dfv cc = dtot(947*TT + t);
        dfv t1 = df_add(df_add(cc, df_mulf(wb, -2.0f)), qf);
        dfv zb = df_addf(df_mulf(df_add(wm2, trX), 0.5f), zetB[t]);
        dfv eb = df_addf(df_mulf(df_add(t1, t2), 0.5f), epsB[t]);
        out[O_ZB + t] = zb.h;
        out[O_EB + t] = eb.h;
    }
}

extern "C" void kernel_launch(void* const* d_in, const int* in_sizes, int n_in,
                              void* d_out, int out_size) {
    const float* Phi  = (const float*)d_in[1];
    const float* Xin  = (const float*)d_in[2];
    const float* Yout = (const float*)d_in[3];
    const float* W    = (const float*)d_in[4];
    const float* B    = (const float*)d_in[5];
    const float* eA   = (const float*)d_in[6];
    const float* eB   = (const float*)d_in[7];
    const float* zA   = (const float*)d_in[8];
    const float* zB   = (const float*)d_in[9];
    int n_total = in_sizes[1] / TT;

    k_reduce<<<NBLK, NTHREADS>>>(Phi, Xin, Yout, W, B, n_total);
    k_sum<<<256, 256>>>(NBLK);
    k_final<<<TT, 256>>>(eA, eB, zA, zB, (float*)d_out);
}